// round 2
// baseline (speedup 1.0000x reference)
#include <cuda_runtime.h>
#include <math.h>

#define S_TOT 16384
#define DIM   1280
#define NH    16
#define HD    80
#define NSEG  16
#define SEGL  1024
#define N_QKV (3 * DIM)

// Scratch (device globals — no allocation allowed)
__device__ float g_q[NH * S_TOT * HD];     // [h][s][d]
__device__ float g_k[NH * S_TOT * HD];
__device__ float g_v[NH * S_TOT * HD];
__device__ float g_attn[S_TOT * DIM];      // [s][h*80+d]

// ---------------------------------------------------------------------------
// Tiled fp32 GEMM: C[M,N] = A[M,K] @ W[N,K]^T + bias
// MODE 0: A = hidden (param), N=3840, epilogue scatters into g_q/g_k/g_v
// MODE 1: A = g_attn,         N=1280, epilogue writes Cout[row*DIM+col]
// BM=BN=64, BK=16, 256 threads, 4x4 microtile.
// ---------------------------------------------------------------------------
template <int MODE>
__global__ __launch_bounds__(256)
void gemm_kernel(const float* __restrict__ Ain,
                 const float* __restrict__ W,
                 const float* __restrict__ bias,
                 float* __restrict__ Cout)
{
    constexpr int NCOLS = (MODE == 0) ? N_QKV : DIM;
    __shared__ float As[16][68];   // [k][m], padded: 68*4B rows keep 16B align, stride-4 banks
    __shared__ float Bs[16][68];   // [k][n]

    const float* A = (MODE == 1) ? g_attn : Ain;

    const int t  = threadIdx.x;
    const int tx = t & 15;         // 0..15 -> 4 cols each
    const int ty = t >> 4;         // 0..15 -> 4 rows each
    const int rowBase = blockIdx.y * 64;
    const int colBase = blockIdx.x * 64;

    const int lr = t >> 2;         // 0..63 row within tile
    const int lc = (t & 3) * 4;    // 0,4,8,12 k-offset

    const float* Aptr = A + (size_t)(rowBase + lr) * DIM + lc;
    const float* Wptr = W + (size_t)(colBase + lr) * DIM + lc;

    float acc[4][4] = {};

    for (int kt = 0; kt < DIM; kt += 16) {
        float4 av = *(const float4*)(Aptr + kt);
        float4 bv = *(const float4*)(Wptr + kt);
        __syncthreads();           // previous tile's compute done
        As[lc + 0][lr] = av.x; As[lc + 1][lr] = av.y;
        As[lc + 2][lr] = av.z; As[lc + 3][lr] = av.w;
        Bs[lc + 0][lr] = bv.x; Bs[lc + 1][lr] = bv.y;
        Bs[lc + 2][lr] = bv.z; Bs[lc + 3][lr] = bv.w;
        __syncthreads();
#pragma unroll
        for (int k = 0; k < 16; k++) {
            float4 a = *(const float4*)&As[k][ty * 4];
            float4 b = *(const float4*)&Bs[k][tx * 4];
            float ar[4] = {a.x, a.y, a.z, a.w};
            float br[4] = {b.x, b.y, b.z, b.w};
#pragma unroll
            for (int i = 0; i < 4; i++)
#pragma unroll
                for (int j = 0; j < 4; j++)
                    acc[i][j] = fmaf(ar[i], br[j], acc[i][j]);
        }
    }

#pragma unroll
    for (int i = 0; i < 4; i++) {
        const int row = rowBase + ty * 4 + i;
#pragma unroll
        for (int j = 0; j < 4; j++) {
            const int col = colBase + tx * 4 + j;
            float v = acc[i][j] + bias[col];
            if (MODE == 1) {
                Cout[(size_t)row * DIM + col] = v;
            } else {
                const int which = col / DIM;
                const int r = col - which * DIM;
                const int h = r / HD;
                const int d = r - h * HD;
                float* dst = (which == 0) ? g_q : (which == 1) ? g_k : g_v;
                dst[((size_t)h * S_TOT + row) * HD + d] = v;
            }
        }
    }
}

// ---------------------------------------------------------------------------
// RoPE on q & k (pairwise d, d+40), plus q *= head_dim^-0.5
// One thread per (h, s, d<40) pair.
// ---------------------------------------------------------------------------
__global__ __launch_bounds__(256)
void rope_kernel(const float* __restrict__ cosb, const float* __restrict__ sinb)
{
    const int idx = blockIdx.x * blockDim.x + threadIdx.x;
    const int total = NH * S_TOT * (HD / 2);
    if (idx >= total) return;
    const int d    = idx % (HD / 2);
    const int rest = idx / (HD / 2);
    const int s = rest % S_TOT;
    const int h = rest / S_TOT;

    const float c0 = cosb[s * HD + d];
    const float c1 = cosb[s * HD + d + 40];
    const float s0 = sinb[s * HD + d];
    const float s1 = sinb[s * HD + d + 40];

    const size_t base = ((size_t)h * S_TOT + s) * HD + d;
    const float scale = 0.11180339887498948f;   // 80^-0.5

    float q0 = g_q[base], q1 = g_q[base + 40];
    g_q[base]      = (q0 * c0 - q1 * s0) * scale;
    g_q[base + 40] = (q1 * c1 + q0 * s1) * scale;

    float k0 = g_k[base], k1 = g_k[base + 40];
    g_k[base]      = k0 * c0 - k1 * s0;
    g_k[base + 40] = k1 * c1 + k0 * s1;
}

// ---------------------------------------------------------------------------
// Flash-style attention per (seg, head, 64-row q-block). 256 threads.
// Score tile 64x64 (4x4 / thread), O accum 64x80 (4x5 / thread).
// ---------------------------------------------------------------------------
__global__ __launch_bounds__(256)
void attn_kernel()
{
    extern __shared__ float sm[];
    float* Qs = sm;                 // 64 x 81
    float* Ks = Qs + 64 * 81;       // 64 x 81
    float* Vs = Ks + 64 * 81;       // 64 x 81
    float* Ps = Vs + 64 * 81;       // 64 x 65

    const int t  = threadIdx.x;
    const int tx = t & 15;
    const int ty = t >> 4;
    const int qb = blockIdx.x;      // 0..15
    const int h  = blockIdx.y;      // 0..15
    const int g  = blockIdx.z;      // 0..15
    const int seqBase = g * SEGL;

    const float* qptr = g_q + ((size_t)h * S_TOT + seqBase + qb * 64) * HD;
    const float* kptr = g_k + ((size_t)h * S_TOT + seqBase) * HD;
    const float* vptr = g_v + ((size_t)h * S_TOT + seqBase) * HD;

    for (int i = t; i < 64 * HD; i += 256) {
        int r = i / HD, c = i - r * HD;
        Qs[r * 81 + c] = qptr[i];
    }

    float m[4], l[4], o[4][5];
#pragma unroll
    for (int i = 0; i < 4; i++) {
        m[i] = -1e30f; l[i] = 0.f;
#pragma unroll
        for (int c = 0; c < 5; c++) o[i][c] = 0.f;
    }

    for (int kc = 0; kc < SEGL; kc += 64) {
        __syncthreads();            // prior iter's Ps/Vs reads done
        for (int i = t; i < 64 * HD; i += 256) {
            int r = i / HD, c = i - r * HD;
            Ks[r * 81 + c] = kptr[(size_t)kc * HD + i];
            Vs[r * 81 + c] = vptr[(size_t)kc * HD + i];
        }
        __syncthreads();

        // QK^T: 64x64 tile
        float sacc[4][4] = {};
#pragma unroll 8
        for (int k = 0; k < HD; k++) {
            float ar[4], br[4];
#pragma unroll
            for (int i = 0; i < 4; i++) ar[i] = Qs[(ty + 16 * i) * 81 + k];
#pragma unroll
            for (int j = 0; j < 4; j++) br[j] = Ks[(tx + 16 * j) * 81 + k];
#pragma unroll
            for (int i = 0; i < 4; i++)
#pragma unroll
                for (int j = 0; j < 4; j++)
                    sacc[i][j] = fmaf(ar[i], br[j], sacc[i][j]);
        }

        // online softmax per row (16-lane groups share a row)
#pragma unroll
        for (int i = 0; i < 4; i++) {
            float mx = sacc[i][0];
#pragma unroll
            for (int j = 1; j < 4; j++) mx = fmaxf(mx, sacc[i][j]);
#pragma unroll
            for (int off = 8; off > 0; off >>= 1)
                mx = fmaxf(mx, __shfl_xor_sync(0xffffffffu, mx, off));
            const float mn = fmaxf(m[i], mx);
            const float corr = __expf(m[i] - mn);
            m[i] = mn;
            float rs = 0.f;
#pragma unroll
            for (int j = 0; j < 4; j++) {
                float p = __expf(sacc[i][j] - mn);
                sacc[i][j] = p;
                rs += p;
            }
#pragma unroll
            for (int off = 8; off > 0; off >>= 1)
                rs += __shfl_xor_sync(0xffffffffu, rs, off);
            l[i] = l[i] * corr + rs;
#pragma unroll
            for (int c = 0; c < 5; c++) o[i][c] *= corr;
#pragma unroll
            for (int j = 0; j < 4; j++)
                Ps[(ty + 16 * i) * 65 + tx + 16 * j] = sacc[i][j];
        }
        __syncthreads();

        // O += P @ V
#pragma unroll 4
        for (int j = 0; j < 64; j++) {
            float pv[4], vv[5];
#pragma unroll
            for (int i = 0; i < 4; i++) pv[i] = Ps[(ty + 16 * i) * 65 + j];
#pragma unroll
            for (int c = 0; c < 5; c++) vv[c] = Vs[j * 81 + tx + 16 * c];
#pragma unroll
            for (int i = 0; i < 4; i++)
#pragma unroll
                for (int c = 0; c < 5; c++)
                    o[i][c] = fmaf(pv[i], vv[c], o[i][c]);
        }
    }

    // epilogue: normalize, write [s][h*80+d]
#pragma unroll
    for (int i = 0; i < 4; i++) {
        const float inv = 1.0f / l[i];
        const int srow = seqBase + qb * 64 + ty + 16 * i;
#pragma unroll
        for (int c = 0; c < 5; c++)
            g_attn[(size_t)srow * DIM + h * HD + tx + 16 * c] = o[i][c] * inv;
    }
}

// ---------------------------------------------------------------------------
extern "C" void kernel_launch(void* const* d_in, const int* in_sizes, int n_in,
                              void* d_out, int out_size)
{
    const float* hidden = (const float*)d_in[0];
    // d_in[1] = cu_seqlens (uniform segments by construction; unused)
    const float* cosb   = (const float*)d_in[2];
    const float* sinb   = (const float*)d_in[3];
    const float* qkv_w  = (const float*)d_in[4];
    const float* qkv_b  = (const float*)d_in[5];
    const float* proj_w = (const float*)d_in[6];
    const float* proj_b = (const float*)d_in[7];
    float* out = (float*)d_out;

    const int attn_smem = (3 * 64 * 81 + 64 * 65) * (int)sizeof(float); // 78848
    cudaFuncSetAttribute(attn_kernel,
                         cudaFuncAttributeMaxDynamicSharedMemorySize, attn_smem);

    // 1) QKV GEMM + bias, scatter to per-head q/k/v
    gemm_kernel<0><<<dim3(N_QKV / 64, S_TOT / 64), 256>>>(hidden, qkv_w, qkv_b, nullptr);

    // 2) RoPE (+ q scaling)
    {
        const int total = NH * S_TOT * (HD / 2);
        rope_kernel<<<(total + 255) / 256, 256>>>(cosb, sinb);
    }

    // 3) attention
    attn_kernel<<<dim3(SEGL / 64, NH, NSEG), 256, attn_smem>>>();

    // 4) output projection
    gemm_kernel<1><<<dim3(DIM / 64, S_TOT / 64), 256>>>(nullptr, proj_w, proj_b, out);
}

// round 4
// speedup vs baseline: 1.9549x; 1.9549x over previous
#include <cuda_runtime.h>
#include <cuda_bf16.h>
#include <cstdint>
#include <math.h>

#define S_TOT 16384
#define DIM   1280
#define NH    16
#define HD    80
#define NSEG  16
#define SEGL  1024
#define N_QKV (3 * DIM)
#define KDIM  1280

// ---------------- scratch (device globals; no runtime alloc) ----------------
__device__ float g_qkv[(size_t)S_TOT * N_QKV];
__device__ float g_q[(size_t)NH * S_TOT * HD];
__device__ float g_k[(size_t)NH * S_TOT * HD];
__device__ float g_v[(size_t)NH * S_TOT * HD];
__device__ float g_attn[(size_t)S_TOT * DIM];
__device__ __nv_bfloat16 g_ahi[(size_t)S_TOT * DIM];
__device__ __nv_bfloat16 g_alo[(size_t)S_TOT * DIM];
__device__ __nv_bfloat16 g_wqhi[(size_t)N_QKV * DIM];
__device__ __nv_bfloat16 g_wqlo[(size_t)N_QKV * DIM];
__device__ __nv_bfloat16 g_wphi[(size_t)DIM * DIM];
__device__ __nv_bfloat16 g_wplo[(size_t)DIM * DIM];

__device__ __forceinline__ uint32_t smem_u32(const void* p) {
    uint32_t a;
    asm("{ .reg .u64 t; cvta.to.shared.u64 t, %1; cvt.u32.u64 %0, t; }" : "=r"(a) : "l"(p));
    return a;
}

// ---------------------------------------------------------------------------
// fp32 -> bf16 hi/lo split
// ---------------------------------------------------------------------------
__global__ __launch_bounds__(256)
void split_kernel(const float* __restrict__ src,
                  __nv_bfloat16* __restrict__ hi,
                  __nv_bfloat16* __restrict__ lo, int n4)
{
    int i = blockIdx.x * blockDim.x + threadIdx.x;
    if (i >= n4) return;
    float4 x = ((const float4*)src)[i];
    __nv_bfloat16 h0 = __float2bfloat16(x.x), h1 = __float2bfloat16(x.y);
    __nv_bfloat16 h2 = __float2bfloat16(x.z), h3 = __float2bfloat16(x.w);
    __nv_bfloat16 l0 = __float2bfloat16(x.x - __bfloat162float(h0));
    __nv_bfloat16 l1 = __float2bfloat16(x.y - __bfloat162float(h1));
    __nv_bfloat16 l2 = __float2bfloat16(x.z - __bfloat162float(h2));
    __nv_bfloat16 l3 = __float2bfloat16(x.w - __bfloat162float(h3));
    ((__nv_bfloat162*)hi)[2 * i]     = __nv_bfloat162(h0, h1);
    ((__nv_bfloat162*)hi)[2 * i + 1] = __nv_bfloat162(h2, h3);
    ((__nv_bfloat162*)lo)[2 * i]     = __nv_bfloat162(l0, l1);
    ((__nv_bfloat162*)lo)[2 * i + 1] = __nv_bfloat162(l2, l3);
}

// ---------------------------------------------------------------------------
// Warp-MMA bf16-split GEMM: C[M,N] = (Ahi+Alo) @ (Bhi+Blo)^T + bias
// BM=BN=128, BK=32. 8 warps (2 x 4), warp tile 64x32, m16n8k16 HMMA.
// SMEM rows padded to 40 bf16 (80B): conflict-free ldmatrix.
// ---------------------------------------------------------------------------
#define LDA 40

__device__ __forceinline__ void ldsm4(uint32_t* f, uint32_t addr) {
    asm volatile("ldmatrix.sync.aligned.m8n8.x4.shared.b16 {%0,%1,%2,%3}, [%4];"
                 : "=r"(f[0]), "=r"(f[1]), "=r"(f[2]), "=r"(f[3]) : "r"(addr));
}
__device__ __forceinline__ void mma16816(float* c, const uint32_t* a, const uint32_t* b) {
    asm volatile("mma.sync.aligned.m16n8k16.row.col.f32.bf16.bf16.f32 "
                 "{%0,%1,%2,%3},{%4,%5,%6,%7},{%8,%9},{%0,%1,%2,%3};"
                 : "+f"(c[0]), "+f"(c[1]), "+f"(c[2]), "+f"(c[3])
                 : "r"(a[0]), "r"(a[1]), "r"(a[2]), "r"(a[3]), "r"(b[0]), "r"(b[1]));
}

__global__ __launch_bounds__(256)
void gemm_mma(const __nv_bfloat16* __restrict__ Ahi, const __nv_bfloat16* __restrict__ Alo,
              const __nv_bfloat16* __restrict__ Bhi, const __nv_bfloat16* __restrict__ Blo,
              const float* __restrict__ bias, float* __restrict__ C, int ldc)
{
    __shared__ __nv_bfloat16 sAhi[128 * LDA];
    __shared__ __nv_bfloat16 sAlo[128 * LDA];
    __shared__ __nv_bfloat16 sBhi[128 * LDA];
    __shared__ __nv_bfloat16 sBlo[128 * LDA];

    const int t    = threadIdx.x;
    const int wid  = t >> 5;
    const int lane = t & 31;
    const int wm   = wid >> 2;           // 0..1 (m)
    const int wn   = wid & 3;            // 0..3 (n)
    const int rowBase = blockIdx.y * 128;
    const int colBase = blockIdx.x * 128;

    const uint32_t bAhi = smem_u32(sAhi);
    const uint32_t bAlo = smem_u32(sAlo);
    const uint32_t bBhi = smem_u32(sBhi);
    const uint32_t bBlo = smem_u32(sBlo);

    // ldmatrix source addresses (byte offsets within tile)
    // A m16k16 tile: rows lane&15, k-half lane>>4
    const uint32_t aRow = wm * 64 + (lane & 15);
    const uint32_t aKof = (lane >> 4) * 16;
    // B x4 covers two n8 tiles: n = nt*16 + (grp>>1)*8 + (lane&7), k-half grp&1
    const uint32_t bRow = wn * 32 + ((lane >> 4) ? 8 : 0) + (lane & 7);
    const uint32_t bKof = ((lane >> 3) & 1) * 16;

    float acc[4][4][4] = {};   // [mt][n8][4]

    // global load indices: idx = t + j*256 -> r = idx>>3, uint2 col = idx&7
    const int glr = t >> 3;
    const int glc = (t & 7) * 4;

    for (int kt = 0; kt < KDIM; kt += 32) {
        // prefetch to regs
        uint2 va[4], vb[4], vc[4], vd[4];
#pragma unroll
        for (int j = 0; j < 4; j++) {
            const int r = glr + j * 32;
            const size_t ga = (size_t)(rowBase + r) * KDIM + kt + glc;
            const size_t gb = (size_t)(colBase + r) * KDIM + kt + glc;
            va[j] = *(const uint2*)(Ahi + ga);
            vb[j] = *(const uint2*)(Alo + ga);
            vc[j] = *(const uint2*)(Bhi + gb);
            vd[j] = *(const uint2*)(Blo + gb);
        }
        __syncthreads();          // prior compute finished reading SMEM
#pragma unroll
        for (int j = 0; j < 4; j++) {
            const int r = glr + j * 32;
            *(uint2*)(sAhi + r * LDA + glc) = va[j];
            *(uint2*)(sAlo + r * LDA + glc) = vb[j];
            *(uint2*)(sBhi + r * LDA + glc) = vc[j];
            *(uint2*)(sBlo + r * LDA + glc) = vd[j];
        }
        __syncthreads();

#pragma unroll
        for (int ks = 0; ks < 2; ks++) {
            const uint32_t ko = ks * 32;  // bytes
            uint32_t ah[4][4], bh[2][4], bl[2][4];
#pragma unroll
            for (int mt = 0; mt < 4; mt++)
                ldsm4(ah[mt], bAhi + (aRow + mt * 16) * (LDA * 2) + ko + aKof);
#pragma unroll
            for (int bt = 0; bt < 2; bt++) {
                ldsm4(bh[bt], bBhi + (bRow + bt * 16) * (LDA * 2) + ko + bKof);
                ldsm4(bl[bt], bBlo + (bRow + bt * 16) * (LDA * 2) + ko + bKof);
            }
            // hi*hi and hi*lo
#pragma unroll
            for (int mt = 0; mt < 4; mt++)
#pragma unroll
                for (int nt = 0; nt < 4; nt++) {
                    mma16816(acc[mt][nt], ah[mt], &bh[nt >> 1][(nt & 1) * 2]);
                    mma16816(acc[mt][nt], ah[mt], &bl[nt >> 1][(nt & 1) * 2]);
                }
            // lo*hi
            uint32_t al[4][4];
#pragma unroll
            for (int mt = 0; mt < 4; mt++)
                ldsm4(al[mt], bAlo + (aRow + mt * 16) * (LDA * 2) + ko + aKof);
#pragma unroll
            for (int mt = 0; mt < 4; mt++)
#pragma unroll
                for (int nt = 0; nt < 4; nt++)
                    mma16816(acc[mt][nt], al[mt], &bh[nt >> 1][(nt & 1) * 2]);
        }
    }

    // epilogue
    const int g   = lane >> 2;           // 0..7
    const int tig = lane & 3;            // 0..3
#pragma unroll
    for (int mt = 0; mt < 4; mt++) {
        const int r0 = rowBase + wm * 64 + mt * 16 + g;
#pragma unroll
        for (int nt = 0; nt < 4; nt++) {
            const int col = colBase + wn * 32 + nt * 8 + tig * 2;
            const float b0 = bias[col], b1 = bias[col + 1];
            float2 o0 = make_float2(acc[mt][nt][0] + b0, acc[mt][nt][1] + b1);
            float2 o1 = make_float2(acc[mt][nt][2] + b0, acc[mt][nt][3] + b1);
            *(float2*)(C + (size_t)r0 * ldc + col)       = o0;
            *(float2*)(C + (size_t)(r0 + 8) * ldc + col) = o1;
        }
    }
}

// ---------------------------------------------------------------------------
// RoPE + scatter: g_qkv[s][3*1280] -> g_q/g_k/g_v [h][s][d] (+ q scaling)
// ---------------------------------------------------------------------------
__global__ __launch_bounds__(256)
void rope_scatter(const float* __restrict__ cosb, const float* __restrict__ sinb)
{
    const int idx = blockIdx.x * blockDim.x + threadIdx.x;
    const int total = NH * S_TOT * (HD / 2);
    if (idx >= total) return;
    const int d    = idx % (HD / 2);
    const int rest = idx / (HD / 2);
    const int s = rest % S_TOT;
    const int h = rest / S_TOT;

    const float c0 = cosb[s * HD + d];
    const float c1 = cosb[s * HD + d + 40];
    const float s0 = sinb[s * HD + d];
    const float s1 = sinb[s * HD + d + 40];

    const size_t src  = (size_t)s * N_QKV + h * HD + d;
    const size_t dstb = ((size_t)h * S_TOT + s) * HD + d;
    const float scale = 0.11180339887498948f;

    float q0 = g_qkv[src],           q1 = g_qkv[src + 40];
    float k0 = g_qkv[src + DIM],     k1 = g_qkv[src + DIM + 40];
    float v0 = g_qkv[src + 2 * DIM], v1 = g_qkv[src + 2 * DIM + 40];

    g_q[dstb]      = (q0 * c0 - q1 * s0) * scale;
    g_q[dstb + 40] = (q1 * c1 + q0 * s1) * scale;
    g_k[dstb]      = k0 * c0 - k1 * s0;
    g_k[dstb + 40] = k1 * c1 + k0 * s1;
    g_v[dstb]      = v0;
    g_v[dstb + 40] = v1;
}

// ---------------------------------------------------------------------------
// Flash-style fp32 attention (proven in R2)
// ---------------------------------------------------------------------------
__global__ __launch_bounds__(256)
void attn_kernel()
{
    extern __shared__ float sm[];
    float* Qs = sm;
    float* Ks = Qs + 64 * 81;
    float* Vs = Ks + 64 * 81;
    float* Ps = Vs + 64 * 81;

    const int t  = threadIdx.x;
    const int tx = t & 15;
    const int ty = t >> 4;
    const int qb = blockIdx.x;
    const int h  = blockIdx.y;
    const int g  = blockIdx.z;
    const int seqBase = g * SEGL;

    const float* qptr = g_q + ((size_t)h * S_TOT + seqBase + qb * 64) * HD;
    const float* kptr = g_k + ((size_t)h * S_TOT + seqBase) * HD;
    const float* vptr = g_v + ((size_t)h * S_TOT + seqBase) * HD;

    for (int i = t; i < 64 * HD; i += 256) {
        int r = i / HD, c = i - r * HD;
        Qs[r * 81 + c] = qptr[i];
    }

    float m[4], l[4], o[4][5];
#pragma unroll
    for (int i = 0; i < 4; i++) {
        m[i] = -1e30f; l[i] = 0.f;
#pragma unroll
        for (int c = 0; c < 5; c++) o[i][c] = 0.f;
    }

    for (int kc = 0; kc < SEGL; kc += 64) {
        __syncthreads();
        for (int i = t; i < 64 * HD; i += 256) {
            int r = i / HD, c = i - r * HD;
            Ks[r * 81 + c] = kptr[(size_t)kc * HD + i];
            Vs[r * 81 + c] = vptr[(size_t)kc * HD + i];
        }
        __syncthreads();

        float sacc[4][4] = {};
#pragma unroll 8
        for (int k = 0; k < HD; k++) {
            float ar[4], br[4];
#pragma unroll
            for (int i = 0; i < 4; i++) ar[i] = Qs[(ty + 16 * i) * 81 + k];
#pragma unroll
            for (int j = 0; j < 4; j++) br[j] = Ks[(tx + 16 * j) * 81 + k];
#pragma unroll
            for (int i = 0; i < 4; i++)
#pragma unroll
                for (int j = 0; j < 4; j++)
                    sacc[i][j] = fmaf(ar[i], br[j], sacc[i][j]);
        }

#pragma unroll
        for (int i = 0; i < 4; i++) {
            float mx = sacc[i][0];
#pragma unroll
            for (int j = 1; j < 4; j++) mx = fmaxf(mx, sacc[i][j]);
#pragma unroll
            for (int off = 8; off > 0; off >>= 1)
                mx = fmaxf(mx, __shfl_xor_sync(0xffffffffu, mx, off));
            const float mn = fmaxf(m[i], mx);
            const float corr = __expf(m[i] - mn);
            m[i] = mn;
            float rs = 0.f;
#pragma unroll
            for (int j = 0; j < 4; j++) {
                float p = __expf(sacc[i][j] - mn);
                sacc[i][j] = p;
                rs += p;
            }
#pragma unroll
            for (int off = 8; off > 0; off >>= 1)
                rs += __shfl_xor_sync(0xffffffffu, rs, off);
            l[i] = l[i] * corr + rs;
#pragma unroll
            for (int c = 0; c < 5; c++) o[i][c] *= corr;
#pragma unroll
            for (int j = 0; j < 4; j++)
                Ps[(ty + 16 * i) * 65 + tx + 16 * j] = sacc[i][j];
        }
        __syncthreads();

#pragma unroll 4
        for (int j = 0; j < 64; j++) {
            float pv[4], vv[5];
#pragma unroll
            for (int i = 0; i < 4; i++) pv[i] = Ps[(ty + 16 * i) * 65 + j];
#pragma unroll
            for (int c = 0; c < 5; c++) vv[c] = Vs[j * 81 + tx + 16 * c];
#pragma unroll
            for (int i = 0; i < 4; i++)
#pragma unroll
                for (int c = 0; c < 5; c++)
                    o[i][c] = fmaf(pv[i], vv[c], o[i][c]);
        }
    }

#pragma unroll
    for (int i = 0; i < 4; i++) {
        const float inv = 1.0f / l[i];
        const int srow = seqBase + qb * 64 + ty + 16 * i;
#pragma unroll
        for (int c = 0; c < 5; c++)
            g_attn[(size_t)srow * DIM + h * HD + tx + 16 * c] = o[i][c] * inv;
    }
}

// ---------------------------------------------------------------------------
extern "C" void kernel_launch(void* const* d_in, const int* in_sizes, int n_in,
                              void* d_out, int out_size)
{
    const float* hidden = (const float*)d_in[0];
    const float* cosb   = (const float*)d_in[2];
    const float* sinb   = (const float*)d_in[3];
    const float* qkv_w  = (const float*)d_in[4];
    const float* qkv_b  = (const float*)d_in[5];
    const float* proj_w = (const float*)d_in[6];
    const float* proj_b = (const float*)d_in[7];
    float* out = (float*)d_out;

    float *p_qkv, *p_attn;
    __nv_bfloat16 *p_ahi, *p_alo, *p_wqhi, *p_wqlo, *p_wphi, *p_wplo;
    cudaGetSymbolAddress((void**)&p_qkv,  g_qkv);
    cudaGetSymbolAddress((void**)&p_attn, g_attn);
    cudaGetSymbolAddress((void**)&p_ahi,  g_ahi);
    cudaGetSymbolAddress((void**)&p_alo,  g_alo);
    cudaGetSymbolAddress((void**)&p_wqhi, g_wqhi);
    cudaGetSymbolAddress((void**)&p_wqlo, g_wqlo);
    cudaGetSymbolAddress((void**)&p_wphi, g_wphi);
    cudaGetSymbolAddress((void**)&p_wplo, g_wplo);

    const int attn_smem = (3 * 64 * 81 + 64 * 65) * (int)sizeof(float);
    cudaFuncSetAttribute(attn_kernel,
                         cudaFuncAttributeMaxDynamicSharedMemorySize, attn_smem);

    // 1) split operands into bf16 hi/lo
    {
        int n4 = S_TOT * DIM / 4;
        split_kernel<<<(n4 + 255) / 256, 256>>>(hidden, p_ahi, p_alo, n4);
        n4 = N_QKV * DIM / 4;
        split_kernel<<<(n4 + 255) / 256, 256>>>(qkv_w, p_wqhi, p_wqlo, n4);
        n4 = DIM * DIM / 4;
        split_kernel<<<(n4 + 255) / 256, 256>>>(proj_w, p_wphi, p_wplo, n4);
    }

    // 2) QKV GEMM (warp-MMA bf16 split) -> g_qkv (+bias)
    gemm_mma<<<dim3(N_QKV / 128, S_TOT / 128), 256>>>(
        p_ahi, p_alo, p_wqhi, p_wqlo, qkv_b, p_qkv, N_QKV);

    // 3) RoPE + scatter
    {
        const int total = NH * S_TOT * (HD / 2);
        rope_scatter<<<(total + 255) / 256, 256>>>(cosb, sinb);
    }

    // 4) attention (fp32 SIMT)
    attn_kernel<<<dim3(SEGL / 64, NH, NSEG), 256, attn_smem>>>();

    // 5) split attention output, then output projection
    {
        int n4 = S_TOT * DIM / 4;
        split_kernel<<<(n4 + 255) / 256, 256>>>(p_attn, p_ahi, p_alo, n4);
    }
    gemm_mma<<<dim3(DIM / 128, S_TOT / 128), 256>>>(
        p_ahi, p_alo, p_wphi, p_wplo, proj_b, out, DIM);
}

// round 5
// speedup vs baseline: 3.0491x; 1.5597x over previous
#include <cuda_runtime.h>
#include <cuda_bf16.h>
#include <cstdint>
#include <math.h>

#define S_TOT 16384
#define DIM   1280
#define NH    16
#define HD    80
#define NSEG  16
#define SEGL  1024
#define N_QKV (3 * DIM)
#define KDIM  1280

// ---------------- scratch (device globals; no runtime alloc) ----------------
__device__ float g_qkv[(size_t)S_TOT * N_QKV];
__device__ __nv_bfloat16 g_qhi[(size_t)NH * S_TOT * HD];   // [h][s][d]
__device__ __nv_bfloat16 g_qlo[(size_t)NH * S_TOT * HD];
__device__ __nv_bfloat16 g_khi[(size_t)NH * S_TOT * HD];
__device__ __nv_bfloat16 g_klo[(size_t)NH * S_TOT * HD];
__device__ __nv_bfloat16 g_vhi[(size_t)DIM * S_TOT];       // [h*80+d][s] (transposed)
__device__ __nv_bfloat16 g_vlo[(size_t)DIM * S_TOT];
__device__ __nv_bfloat16 g_ahi[(size_t)S_TOT * DIM];       // activations (hidden / attn-out)
__device__ __nv_bfloat16 g_alo[(size_t)S_TOT * DIM];
__device__ __nv_bfloat16 g_wqhi[(size_t)N_QKV * DIM];
__device__ __nv_bfloat16 g_wqlo[(size_t)N_QKV * DIM];
__device__ __nv_bfloat16 g_wphi[(size_t)DIM * DIM];
__device__ __nv_bfloat16 g_wplo[(size_t)DIM * DIM];

__device__ __forceinline__ uint32_t smem_u32(const void* p) {
    uint32_t a;
    asm("{ .reg .u64 t; cvta.to.shared.u64 t, %1; cvt.u32.u64 %0, t; }" : "=r"(a) : "l"(p));
    return a;
}
__device__ __forceinline__ void ldsm4(uint32_t* f, uint32_t addr) {
    asm volatile("ldmatrix.sync.aligned.m8n8.x4.shared.b16 {%0,%1,%2,%3}, [%4];"
                 : "=r"(f[0]), "=r"(f[1]), "=r"(f[2]), "=r"(f[3]) : "r"(addr));
}
__device__ __forceinline__ void mma16816(float* c, const uint32_t* a, const uint32_t* b) {
    asm volatile("mma.sync.aligned.m16n8k16.row.col.f32.bf16.bf16.f32 "
                 "{%0,%1,%2,%3},{%4,%5,%6,%7},{%8,%9},{%0,%1,%2,%3};"
                 : "+f"(c[0]), "+f"(c[1]), "+f"(c[2]), "+f"(c[3])
                 : "r"(a[0]), "r"(a[1]), "r"(a[2]), "r"(a[3]), "r"(b[0]), "r"(b[1]));
}
__device__ __forceinline__ void split2(float x, __nv_bfloat16& h, __nv_bfloat16& l) {
    h = __float2bfloat16(x);
    l = __float2bfloat16(x - __bfloat162float(h));
}

// ---------------------------------------------------------------------------
// fp32 -> bf16 hi/lo split
// ---------------------------------------------------------------------------
__global__ __launch_bounds__(256)
void split_kernel(const float* __restrict__ src,
                  __nv_bfloat16* __restrict__ hi,
                  __nv_bfloat16* __restrict__ lo, int n4)
{
    int i = blockIdx.x * blockDim.x + threadIdx.x;
    if (i >= n4) return;
    float4 x = ((const float4*)src)[i];
    __nv_bfloat16 h0, h1, h2, h3, l0, l1, l2, l3;
    split2(x.x, h0, l0); split2(x.y, h1, l1);
    split2(x.z, h2, l2); split2(x.w, h3, l3);
    ((__nv_bfloat162*)hi)[2 * i]     = __nv_bfloat162(h0, h1);
    ((__nv_bfloat162*)hi)[2 * i + 1] = __nv_bfloat162(h2, h3);
    ((__nv_bfloat162*)lo)[2 * i]     = __nv_bfloat162(l0, l1);
    ((__nv_bfloat162*)lo)[2 * i + 1] = __nv_bfloat162(l2, l3);
}

// ---------------------------------------------------------------------------
// Warp-MMA bf16-split GEMM (unchanged from R4 — proven)
// ---------------------------------------------------------------------------
#define LDA 40

__global__ __launch_bounds__(256)
void gemm_mma(const __nv_bfloat16* __restrict__ Ahi, const __nv_bfloat16* __restrict__ Alo,
              const __nv_bfloat16* __restrict__ Bhi, const __nv_bfloat16* __restrict__ Blo,
              const float* __restrict__ bias, float* __restrict__ C, int ldc)
{
    __shared__ __nv_bfloat16 sAhi[128 * LDA];
    __shared__ __nv_bfloat16 sAlo[128 * LDA];
    __shared__ __nv_bfloat16 sBhi[128 * LDA];
    __shared__ __nv_bfloat16 sBlo[128 * LDA];

    const int t    = threadIdx.x;
    const int wid  = t >> 5;
    const int lane = t & 31;
    const int wm   = wid >> 2;
    const int wn   = wid & 3;
    const int rowBase = blockIdx.y * 128;
    const int colBase = blockIdx.x * 128;

    const uint32_t bAhi = smem_u32(sAhi);
    const uint32_t bAlo = smem_u32(sAlo);
    const uint32_t bBhi = smem_u32(sBhi);
    const uint32_t bBlo = smem_u32(sBlo);

    const uint32_t aRow = wm * 64 + (lane & 15);
    const uint32_t aKof = (lane >> 4) * 16;
    const uint32_t bRow = wn * 32 + ((lane >> 4) ? 8 : 0) + (lane & 7);
    const uint32_t bKof = ((lane >> 3) & 1) * 16;

    float acc[4][4][4] = {};

    const int glr = t >> 3;
    const int glc = (t & 7) * 4;

    for (int kt = 0; kt < KDIM; kt += 32) {
        uint2 va[4], vb[4], vc[4], vd[4];
#pragma unroll
        for (int j = 0; j < 4; j++) {
            const int r = glr + j * 32;
            const size_t ga = (size_t)(rowBase + r) * KDIM + kt + glc;
            const size_t gb = (size_t)(colBase + r) * KDIM + kt + glc;
            va[j] = *(const uint2*)(Ahi + ga);
            vb[j] = *(const uint2*)(Alo + ga);
            vc[j] = *(const uint2*)(Bhi + gb);
            vd[j] = *(const uint2*)(Blo + gb);
        }
        __syncthreads();
#pragma unroll
        for (int j = 0; j < 4; j++) {
            const int r = glr + j * 32;
            *(uint2*)(sAhi + r * LDA + glc) = va[j];
            *(uint2*)(sAlo + r * LDA + glc) = vb[j];
            *(uint2*)(sBhi + r * LDA + glc) = vc[j];
            *(uint2*)(sBlo + r * LDA + glc) = vd[j];
        }
        __syncthreads();

#pragma unroll
        for (int ks = 0; ks < 2; ks++) {
            const uint32_t ko = ks * 32;
            uint32_t ah[4][4], bh[2][4], bl[2][4];
#pragma unroll
            for (int mt = 0; mt < 4; mt++)
                ldsm4(ah[mt], bAhi + (aRow + mt * 16) * (LDA * 2) + ko + aKof);
#pragma unroll
            for (int bt = 0; bt < 2; bt++) {
                ldsm4(bh[bt], bBhi + (bRow + bt * 16) * (LDA * 2) + ko + bKof);
                ldsm4(bl[bt], bBlo + (bRow + bt * 16) * (LDA * 2) + ko + bKof);
            }
#pragma unroll
            for (int mt = 0; mt < 4; mt++)
#pragma unroll
                for (int nt = 0; nt < 4; nt++) {
                    mma16816(acc[mt][nt], ah[mt], &bh[nt >> 1][(nt & 1) * 2]);
                    mma16816(acc[mt][nt], ah[mt], &bl[nt >> 1][(nt & 1) * 2]);
                }
            uint32_t al[4][4];
#pragma unroll
            for (int mt = 0; mt < 4; mt++)
                ldsm4(al[mt], bAlo + (aRow + mt * 16) * (LDA * 2) + ko + aKof);
#pragma unroll
            for (int mt = 0; mt < 4; mt++)
#pragma unroll
                for (int nt = 0; nt < 4; nt++)
                    mma16816(acc[mt][nt], al[mt], &bh[nt >> 1][(nt & 1) * 2]);
        }
    }

    const int g   = lane >> 2;
    const int tig = lane & 3;
#pragma unroll
    for (int mt = 0; mt < 4; mt++) {
        const int r0 = rowBase + wm * 64 + mt * 16 + g;
#pragma unroll
        for (int nt = 0; nt < 4; nt++) {
            const int col = colBase + wn * 32 + nt * 8 + tig * 2;
            const float b0 = bias[col], b1 = bias[col + 1];
            float2 o0 = make_float2(acc[mt][nt][0] + b0, acc[mt][nt][1] + b1);
            float2 o1 = make_float2(acc[mt][nt][2] + b0, acc[mt][nt][3] + b1);
            *(float2*)(C + (size_t)r0 * ldc + col)       = o0;
            *(float2*)(C + (size_t)(r0 + 8) * ldc + col) = o1;
        }
    }
}

// ---------------------------------------------------------------------------
// RoPE + scatter to bf16 hi/lo: g_qkv -> g_q{hi,lo}, g_k{hi,lo} [h][s][d]
// ---------------------------------------------------------------------------
__global__ __launch_bounds__(256)
void rope_scatter(const float* __restrict__ cosb, const float* __restrict__ sinb)
{
    const int idx = blockIdx.x * blockDim.x + threadIdx.x;
    const int total = NH * S_TOT * (HD / 2);
    if (idx >= total) return;
    const int d    = idx % (HD / 2);
    const int rest = idx / (HD / 2);
    const int s = rest % S_TOT;
    const int h = rest / S_TOT;

    const float c0 = cosb[s * HD + d];
    const float c1 = cosb[s * HD + d + 40];
    const float s0 = sinb[s * HD + d];
    const float s1 = sinb[s * HD + d + 40];

    const size_t src  = (size_t)s * N_QKV + h * HD + d;
    const size_t dstb = ((size_t)h * S_TOT + s) * HD + d;
    const float scale = 0.11180339887498948f;

    float q0 = g_qkv[src],       q1 = g_qkv[src + 40];
    float k0 = g_qkv[src + DIM], k1 = g_qkv[src + DIM + 40];

    float qa = (q0 * c0 - q1 * s0) * scale;
    float qb = (q1 * c1 + q0 * s1) * scale;
    float ka = k0 * c0 - k1 * s0;
    float kb = k1 * c1 + k0 * s1;

    __nv_bfloat16 h_, l_;
    split2(qa, h_, l_); g_qhi[dstb] = h_;      g_qlo[dstb] = l_;
    split2(qb, h_, l_); g_qhi[dstb + 40] = h_; g_qlo[dstb + 40] = l_;
    split2(ka, h_, l_); g_khi[dstb] = h_;      g_klo[dstb] = l_;
    split2(kb, h_, l_); g_khi[dstb + 40] = h_; g_klo[dstb + 40] = l_;
}

// ---------------------------------------------------------------------------
// V: split + transpose  g_qkv[s][2*DIM + hd] -> g_v{hi,lo}[hd][s]
// 32x32 tiles via smem.
// ---------------------------------------------------------------------------
__global__ __launch_bounds__(256)
void v_split_t()
{
    __shared__ float tile[32][33];
    const int t = threadIdx.x;
    const int sBase  = blockIdx.x * 32;
    const int hdBase = blockIdx.y * 32;

    const int tx = t & 31, ty = t >> 5;
#pragma unroll
    for (int j = 0; j < 4; j++) {
        const int r = ty + j * 8;      // s offset
        tile[r][tx] = g_qkv[(size_t)(sBase + r) * N_QKV + 2 * DIM + hdBase + tx];
    }
    __syncthreads();

    const int r2 = t >> 3;             // hd offset 0..31
    const int sp = (t & 7) * 4;        // s offset 0..28
    __nv_bfloat16 h0, h1, h2, h3, l0, l1, l2, l3;
    split2(tile[sp + 0][r2], h0, l0);
    split2(tile[sp + 1][r2], h1, l1);
    split2(tile[sp + 2][r2], h2, l2);
    split2(tile[sp + 3][r2], h3, l3);
    const size_t o = (size_t)(hdBase + r2) * S_TOT + sBase + sp;
    *(__nv_bfloat162*)(g_vhi + o)     = __nv_bfloat162(h0, h1);
    *(__nv_bfloat162*)(g_vhi + o + 2) = __nv_bfloat162(h2, h3);
    *(__nv_bfloat162*)(g_vlo + o)     = __nv_bfloat162(l0, l1);
    *(__nv_bfloat162*)(g_vlo + o + 2) = __nv_bfloat162(l2, l3);
}

// ---------------------------------------------------------------------------
// Tensor-core flash attention, bf16 hi/lo split everywhere.
// CTA: 128 q-rows, loops kv in 128-chunks. 8 warps (16 rows each).
// ---------------------------------------------------------------------------
#define LQK 88     // row pitch (bf16) for Q/K tiles (80 cols + pad)
#define LP  136    // row pitch for P (128 cols + pad) and V (128 kv cols + pad)

#define OQH 0
#define OQL (OQH + 128 * LQK * 2)
#define OKH (OQL + 128 * LQK * 2)
#define OKL (OKH + 128 * LQK * 2)
#define OVH (OKL + 128 * LQK * 2)
#define OVL (OVH + 80 * LP * 2)
#define OPH (OVL + 80 * LP * 2)
#define OPL (OPH + 128 * LP * 2)
#define ATTN_SMEM (OPL + 128 * LP * 2)   // 203264 bytes

__global__ __launch_bounds__(256)
void attn_mma()
{
    extern __shared__ char sm[];
    const uint32_t sb = smem_u32(sm);
    const int t    = threadIdx.x;
    const int wid  = t >> 5;
    const int lane = t & 31;
    const int qb = blockIdx.x, h = blockIdx.y, seg = blockIdx.z;
    const int segBase = seg * SEGL;
    const int s0 = segBase + qb * 128;

    const size_t qBase = ((size_t)h * S_TOT + s0) * HD;

    // load Q tiles (persistent)
    for (int i = t; i < 128 * 20; i += 256) {
        const int r = i / 20, c4 = (i % 20) * 4;
        const size_t ga = qBase + (size_t)r * HD + c4;
        const uint32_t so = r * (LQK * 2) + c4 * 2;
        *(uint2*)(sm + OQH + so) = *(const uint2*)(g_qhi + ga);
        *(uint2*)(sm + OQL + so) = *(const uint2*)(g_qlo + ga);
    }

    // fragment addresses
    const uint32_t aRowOff = (wid * 16 + (lane & 15));
    const uint32_t aKof = (lane >> 4) * 16;
    const uint32_t bRowSub = ((lane >> 4) ? 8 : 0) + (lane & 7);
    const uint32_t bKof = ((lane >> 3) & 1) * 16;

    const int g   = lane >> 2;     // row-in-16 (and +8)
    const int tig = lane & 3;

    float m0 = -1e30f, m1 = -1e30f, l0 = 0.f, l1 = 0.f;
    float oacc[10][4] = {};

    for (int kc = 0; kc < SEGL; kc += 128) {
        __syncthreads();   // previous iteration's PV done reading K/V/P
        // load K (128x80) and V^T (80x128) tiles
        for (int i = t; i < 128 * 20; i += 256) {
            const int r = i / 20, c4 = (i % 20) * 4;
            const size_t ga = ((size_t)h * S_TOT + segBase + kc + r) * HD + c4;
            const uint32_t so = r * (LQK * 2) + c4 * 2;
            *(uint2*)(sm + OKH + so) = *(const uint2*)(g_khi + ga);
            *(uint2*)(sm + OKL + so) = *(const uint2*)(g_klo + ga);
        }
        for (int i = t; i < 80 * 32; i += 256) {
            const int r = i / 32, c4 = (i % 32) * 4;
            const size_t ga = ((size_t)(h * HD + r)) * S_TOT + segBase + kc + c4;
            const uint32_t so = r * (LP * 2) + c4 * 2;
            *(uint2*)(sm + OVH + so) = *(const uint2*)(g_vhi + ga);
            *(uint2*)(sm + OVL + so) = *(const uint2*)(g_vlo + ga);
        }
        __syncthreads();

        // ---- S = Q K^T (128x128, warp: 16 rows) ----
        float acc[16][4];
#pragma unroll
        for (int nt = 0; nt < 16; nt++)
#pragma unroll
            for (int c = 0; c < 4; c++) acc[nt][c] = 0.f;

#pragma unroll
        for (int ks = 0; ks < 5; ks++) {
            const uint32_t ko = ks * 32;
            uint32_t qh[4], ql[4];
            ldsm4(qh, sb + OQH + aRowOff * (LQK * 2) + ko + aKof);
            ldsm4(ql, sb + OQL + aRowOff * (LQK * 2) + ko + aKof);
#pragma unroll
            for (int bt = 0; bt < 8; bt++) {
                uint32_t kh[4], kl[4];
                const uint32_t br = (bt * 16 + bRowSub) * (LQK * 2) + ko + bKof;
                ldsm4(kh, sb + OKH + br);
                ldsm4(kl, sb + OKL + br);
                mma16816(acc[2 * bt],     qh, kh + 0);
                mma16816(acc[2 * bt + 1], qh, kh + 2);
                mma16816(acc[2 * bt],     qh, kl + 0);
                mma16816(acc[2 * bt + 1], qh, kl + 2);
                mma16816(acc[2 * bt],     ql, kh + 0);
                mma16816(acc[2 * bt + 1], ql, kh + 2);
            }
        }

        // ---- online softmax (rows g and g+8 of warp tile) ----
        float mx0 = -1e30f, mx1 = -1e30f;
#pragma unroll
        for (int nt = 0; nt < 16; nt++) {
            mx0 = fmaxf(mx0, fmaxf(acc[nt][0], acc[nt][1]));
            mx1 = fmaxf(mx1, fmaxf(acc[nt][2], acc[nt][3]));
        }
        mx0 = fmaxf(mx0, __shfl_xor_sync(0xffffffffu, mx0, 1));
        mx0 = fmaxf(mx0, __shfl_xor_sync(0xffffffffu, mx0, 2));
        mx1 = fmaxf(mx1, __shfl_xor_sync(0xffffffffu, mx1, 1));
        mx1 = fmaxf(mx1, __shfl_xor_sync(0xffffffffu, mx1, 2));

        const float mn0 = fmaxf(m0, mx0);
        const float mn1 = fmaxf(m1, mx1);
        const float cr0 = __expf(m0 - mn0);
        const float cr1 = __expf(m1 - mn1);
        m0 = mn0; m1 = mn1;

        float rs0 = 0.f, rs1 = 0.f;
#pragma unroll
        for (int nt = 0; nt < 16; nt++) {
            acc[nt][0] = __expf(acc[nt][0] - mn0);
            acc[nt][1] = __expf(acc[nt][1] - mn0);
            acc[nt][2] = __expf(acc[nt][2] - mn1);
            acc[nt][3] = __expf(acc[nt][3] - mn1);
            rs0 += acc[nt][0] + acc[nt][1];
            rs1 += acc[nt][2] + acc[nt][3];
        }
        rs0 += __shfl_xor_sync(0xffffffffu, rs0, 1);
        rs0 += __shfl_xor_sync(0xffffffffu, rs0, 2);
        rs1 += __shfl_xor_sync(0xffffffffu, rs1, 1);
        rs1 += __shfl_xor_sync(0xffffffffu, rs1, 2);
        l0 = l0 * cr0 + rs0;
        l1 = l1 * cr1 + rs1;

#pragma unroll
        for (int vt = 0; vt < 10; vt++) {
            oacc[vt][0] *= cr0; oacc[vt][1] *= cr0;
            oacc[vt][2] *= cr1; oacc[vt][3] *= cr1;
        }

        // ---- write P hi/lo to smem ----
        const uint32_t pr0 = (wid * 16 + g) * (LP * 2);
        const uint32_t pr1 = pr0 + 8 * (LP * 2);
#pragma unroll
        for (int nt = 0; nt < 16; nt++) {
            const uint32_t co = (nt * 8 + tig * 2) * 2;
            __nv_bfloat16 ph0, pl0, ph1, pl1;
            split2(acc[nt][0], ph0, pl0);
            split2(acc[nt][1], ph1, pl1);
            *(__nv_bfloat162*)(sm + OPH + pr0 + co) = __nv_bfloat162(ph0, ph1);
            *(__nv_bfloat162*)(sm + OPL + pr0 + co) = __nv_bfloat162(pl0, pl1);
            split2(acc[nt][2], ph0, pl0);
            split2(acc[nt][3], ph1, pl1);
            *(__nv_bfloat162*)(sm + OPH + pr1 + co) = __nv_bfloat162(ph0, ph1);
            *(__nv_bfloat162*)(sm + OPL + pr1 + co) = __nv_bfloat162(pl0, pl1);
        }
        __syncwarp();   // warp reads only its own P rows

        // ---- O += P V  (warp: 16 rows x 80 cols) ----
#pragma unroll
        for (int ks = 0; ks < 8; ks++) {
            const uint32_t ko = ks * 32;
            uint32_t ph[4], pl[4];
            ldsm4(ph, sb + OPH + aRowOff * (LP * 2) + ko + aKof);
            ldsm4(pl, sb + OPL + aRowOff * (LP * 2) + ko + aKof);
#pragma unroll
            for (int bt = 0; bt < 5; bt++) {
                uint32_t vh[4], vl[4];
                const uint32_t br = (bt * 16 + bRowSub) * (LP * 2) + ko + bKof;
                ldsm4(vh, sb + OVH + br);
                ldsm4(vl, sb + OVL + br);
                mma16816(oacc[2 * bt],     ph, vh + 0);
                mma16816(oacc[2 * bt + 1], ph, vh + 2);
                mma16816(oacc[2 * bt],     ph, vl + 0);
                mma16816(oacc[2 * bt + 1], ph, vl + 2);
                mma16816(oacc[2 * bt],     pl, vh + 0);
                mma16816(oacc[2 * bt + 1], pl, vh + 2);
            }
        }
    }

    // ---- epilogue: normalize, split, write proj-GEMM A operand ----
    const float inv0 = 1.0f / l0;
    const float inv1 = 1.0f / l1;
    const int srow0 = s0 + wid * 16 + g;
    const int srow1 = srow0 + 8;
#pragma unroll
    for (int vt = 0; vt < 10; vt++) {
        const int col = h * HD + vt * 8 + tig * 2;
        __nv_bfloat16 h0, l0v, h1, l1v;
        split2(oacc[vt][0] * inv0, h0, l0v);
        split2(oacc[vt][1] * inv0, h1, l1v);
        *(__nv_bfloat162*)(g_ahi + (size_t)srow0 * DIM + col) = __nv_bfloat162(h0, h1);
        *(__nv_bfloat162*)(g_alo + (size_t)srow0 * DIM + col) = __nv_bfloat162(l0v, l1v);
        split2(oacc[vt][2] * inv1, h0, l0v);
        split2(oacc[vt][3] * inv1, h1, l1v);
        *(__nv_bfloat162*)(g_ahi + (size_t)srow1 * DIM + col) = __nv_bfloat162(h0, h1);
        *(__nv_bfloat162*)(g_alo + (size_t)srow1 * DIM + col) = __nv_bfloat162(l1 == l1 ? l0v : l0v, l1v);
    }
}

// ---------------------------------------------------------------------------
extern "C" void kernel_launch(void* const* d_in, const int* in_sizes, int n_in,
                              void* d_out, int out_size)
{
    const float* hidden = (const float*)d_in[0];
    const float* cosb   = (const float*)d_in[2];
    const float* sinb   = (const float*)d_in[3];
    const float* qkv_w  = (const float*)d_in[4];
    const float* qkv_b  = (const float*)d_in[5];
    const float* proj_w = (const float*)d_in[6];
    const float* proj_b = (const float*)d_in[7];
    float* out = (float*)d_out;

    float* p_qkv;
    __nv_bfloat16 *p_ahi, *p_alo, *p_wqhi, *p_wqlo, *p_wphi, *p_wplo;
    cudaGetSymbolAddress((void**)&p_qkv,  g_qkv);
    cudaGetSymbolAddress((void**)&p_ahi,  g_ahi);
    cudaGetSymbolAddress((void**)&p_alo,  g_alo);
    cudaGetSymbolAddress((void**)&p_wqhi, g_wqhi);
    cudaGetSymbolAddress((void**)&p_wqlo, g_wqlo);
    cudaGetSymbolAddress((void**)&p_wphi, g_wphi);
    cudaGetSymbolAddress((void**)&p_wplo, g_wplo);

    cudaFuncSetAttribute(attn_mma,
                         cudaFuncAttributeMaxDynamicSharedMemorySize, ATTN_SMEM);

    // 1) split inputs to bf16 hi/lo
    {
        int n4 = S_TOT * DIM / 4;
        split_kernel<<<(n4 + 255) / 256, 256>>>(hidden, p_ahi, p_alo, n4);
        n4 = N_QKV * DIM / 4;
        split_kernel<<<(n4 + 255) / 256, 256>>>(qkv_w, p_wqhi, p_wqlo, n4);
        n4 = DIM * DIM / 4;
        split_kernel<<<(n4 + 255) / 256, 256>>>(proj_w, p_wphi, p_wplo, n4);
    }

    // 2) QKV GEMM
    gemm_mma<<<dim3(N_QKV / 128, S_TOT / 128), 256>>>(
        p_ahi, p_alo, p_wqhi, p_wqlo, qkv_b, p_qkv, N_QKV);

    // 3) RoPE+split (q,k) and V transpose+split
    {
        const int total = NH * S_TOT * (HD / 2);
        rope_scatter<<<(total + 255) / 256, 256>>>(cosb, sinb);
        v_split_t<<<dim3(S_TOT / 32, DIM / 32), 256>>>();
    }

    // 4) attention (tensor-core, hi/lo split) -> writes g_ahi/g_alo directly
    attn_mma<<<dim3(SEGL / 128, NH, NSEG), 256, ATTN_SMEM>>>();

    // 5) output projection
    gemm_mma<<<dim3(DIM / 128, S_TOT / 128), 256>>>(
        p_ahi, p_alo, p_wphi, p_wplo, proj_b, out, DIM);
}

// round 6
// speedup vs baseline: 3.6248x; 1.1888x over previous
#include <cuda_runtime.h>
#include <cuda_bf16.h>
#include <cstdint>
#include <math.h>

#define S_TOT 16384
#define DIM   1280
#define NH    16
#define HD    80
#define NSEG  16
#define SEGL  1024
#define N_QKV (3 * DIM)
#define KDIM  1280

// ---------------- scratch (device globals; no runtime alloc) ----------------
__device__ float g_qkv[(size_t)S_TOT * N_QKV];
__device__ __nv_bfloat16 g_qhi[(size_t)NH * S_TOT * HD];   // [h][s][d]
__device__ __nv_bfloat16 g_qlo[(size_t)NH * S_TOT * HD];
__device__ __nv_bfloat16 g_khi[(size_t)NH * S_TOT * HD];
__device__ __nv_bfloat16 g_klo[(size_t)NH * S_TOT * HD];
__device__ __nv_bfloat16 g_vhi[(size_t)DIM * S_TOT];       // [h*80+d][s]
__device__ __nv_bfloat16 g_vlo[(size_t)DIM * S_TOT];
__device__ __nv_bfloat16 g_ahi[(size_t)S_TOT * DIM];
__device__ __nv_bfloat16 g_alo[(size_t)S_TOT * DIM];
__device__ __nv_bfloat16 g_wqhi[(size_t)N_QKV * DIM];
__device__ __nv_bfloat16 g_wqlo[(size_t)N_QKV * DIM];
__device__ __nv_bfloat16 g_wphi[(size_t)DIM * DIM];
__device__ __nv_bfloat16 g_wplo[(size_t)DIM * DIM];

__device__ __forceinline__ uint32_t smem_u32(const void* p) {
    uint32_t a;
    asm("{ .reg .u64 t; cvta.to.shared.u64 t, %1; cvt.u32.u64 %0, t; }" : "=r"(a) : "l"(p));
    return a;
}
__device__ __forceinline__ void ldsm4(uint32_t* f, uint32_t addr) {
    asm volatile("ldmatrix.sync.aligned.m8n8.x4.shared.b16 {%0,%1,%2,%3}, [%4];"
                 : "=r"(f[0]), "=r"(f[1]), "=r"(f[2]), "=r"(f[3]) : "r"(addr));
}
__device__ __forceinline__ void mma16816(float* c, const uint32_t* a, const uint32_t* b) {
    asm volatile("mma.sync.aligned.m16n8k16.row.col.f32.bf16.bf16.f32 "
                 "{%0,%1,%2,%3},{%4,%5,%6,%7},{%8,%9},{%0,%1,%2,%3};"
                 : "+f"(c[0]), "+f"(c[1]), "+f"(c[2]), "+f"(c[3])
                 : "r"(a[0]), "r"(a[1]), "r"(a[2]), "r"(a[3]), "r"(b[0]), "r"(b[1]));
}
__device__ __forceinline__ void split2(float x, __nv_bfloat16& h, __nv_bfloat16& l) {
    h = __float2bfloat16(x);
    l = __float2bfloat16(x - __bfloat162float(h));
}
// pack two fp32 into bf16x2 hi reg + bf16x2 lo-residual reg
__device__ __forceinline__ void packsplit(float x, float y, uint32_t& h, uint32_t& l) {
    __nv_bfloat16 hx, hy, lx, ly;
    split2(x, hx, lx); split2(y, hy, ly);
    __nv_bfloat162 hv(hx, hy), lv(lx, ly);
    h = *(uint32_t*)&hv;
    l = *(uint32_t*)&lv;
}
__device__ __forceinline__ void cpa16(uint32_t s, const void* g) {
    asm volatile("cp.async.cg.shared.global [%0], [%1], 16;" :: "r"(s), "l"(g));
}
__device__ __forceinline__ void cpa_commit() {
    asm volatile("cp.async.commit_group;" ::: "memory");
}
template <int N> __device__ __forceinline__ void cpa_wait() {
    asm volatile("cp.async.wait_group %0;" :: "n"(N) : "memory");
}

// ---------------------------------------------------------------------------
// fp32 -> bf16 hi/lo split
// ---------------------------------------------------------------------------
__global__ __launch_bounds__(256)
void split_kernel(const float* __restrict__ src,
                  __nv_bfloat16* __restrict__ hi,
                  __nv_bfloat16* __restrict__ lo, int n4)
{
    int i = blockIdx.x * blockDim.x + threadIdx.x;
    if (i >= n4) return;
    float4 x = ((const float4*)src)[i];
    __nv_bfloat16 h0, h1, h2, h3, l0, l1, l2, l3;
    split2(x.x, h0, l0); split2(x.y, h1, l1);
    split2(x.z, h2, l2); split2(x.w, h3, l3);
    ((__nv_bfloat162*)hi)[2 * i]     = __nv_bfloat162(h0, h1);
    ((__nv_bfloat162*)hi)[2 * i + 1] = __nv_bfloat162(h2, h3);
    ((__nv_bfloat162*)lo)[2 * i]     = __nv_bfloat162(l0, l1);
    ((__nv_bfloat162*)lo)[2 * i + 1] = __nv_bfloat162(l2, l3);
}

// ---------------------------------------------------------------------------
// Warp-MMA bf16-split GEMM, 2-stage cp.async pipeline.
// BM=BN=128, BK=32, 8 warps (2x4), warp tile 64x32.
// Dynamic SMEM: 2 stages x 4 tiles x (128 x 40 bf16) = 81920 B.
// ---------------------------------------------------------------------------
#define GTILE  10240              // bytes per (128 x 40bf16) tile
#define GSTAGE 40960              // 4 tiles
#define GEMM_SMEM (2 * GSTAGE)

__global__ __launch_bounds__(256)
void gemm_mma(const __nv_bfloat16* __restrict__ Ahi, const __nv_bfloat16* __restrict__ Alo,
              const __nv_bfloat16* __restrict__ Bhi, const __nv_bfloat16* __restrict__ Blo,
              const float* __restrict__ bias, float* __restrict__ C, int ldc)
{
    extern __shared__ char gsm[];
    const uint32_t sb = smem_u32(gsm);

    const int t    = threadIdx.x;
    const int wid  = t >> 5;
    const int lane = t & 31;
    const int wm   = wid >> 2;
    const int wn   = wid & 3;
    const int rowBase = blockIdx.y * 128;
    const int colBase = blockIdx.x * 128;

    const uint32_t aRow = wm * 64 + (lane & 15);
    const uint32_t aKof = (lane >> 4) * 16;
    const uint32_t bRow = wn * 32 + ((lane >> 4) ? 8 : 0) + (lane & 7);
    const uint32_t bKof = ((lane >> 3) & 1) * 16;

    float acc[4][4][4] = {};

    // issue one stage's loads (8 cp.async / thread)
    auto issue = [&](int stage, int kt) {
        const uint32_t s0 = sb + stage * GSTAGE;
#pragma unroll
        for (int j = 0; j < 2; j++) {
            const int idx = t + j * 256;       // 0..511
            const int r  = idx >> 2;           // 0..127
            const int c8 = (idx & 3) * 8;      // bf16 col 0,8,16,24
            const size_t ga = (size_t)(rowBase + r) * KDIM + kt + c8;
            const size_t gb = (size_t)(colBase + r) * KDIM + kt + c8;
            const uint32_t so = r * 80 + c8 * 2;
            cpa16(s0 + 0 * GTILE + so, Ahi + ga);
            cpa16(s0 + 1 * GTILE + so, Alo + ga);
            cpa16(s0 + 2 * GTILE + so, Bhi + gb);
            cpa16(s0 + 3 * GTILE + so, Blo + gb);
        }
        cpa_commit();
    };

    issue(0, 0);
    const int NT = KDIM / 32;    // 40
    for (int it = 0; it < NT; it++) {
        if (it + 1 < NT) { issue((it + 1) & 1, (it + 1) * 32); cpa_wait<1>(); }
        else             { cpa_wait<0>(); }
        __syncthreads();

        const uint32_t s0 = sb + (it & 1) * GSTAGE;
        const uint32_t pAhi = s0, pAlo = s0 + GTILE, pBhi = s0 + 2 * GTILE, pBlo = s0 + 3 * GTILE;
#pragma unroll
        for (int ks = 0; ks < 2; ks++) {
            const uint32_t ko = ks * 32;
            uint32_t ah[4][4], bh[2][4], bl[2][4];
#pragma unroll
            for (int mt = 0; mt < 4; mt++)
                ldsm4(ah[mt], pAhi + (aRow + mt * 16) * 80 + ko + aKof);
#pragma unroll
            for (int bt = 0; bt < 2; bt++) {
                ldsm4(bh[bt], pBhi + (bRow + bt * 16) * 80 + ko + bKof);
                ldsm4(bl[bt], pBlo + (bRow + bt * 16) * 80 + ko + bKof);
            }
#pragma unroll
            for (int mt = 0; mt < 4; mt++)
#pragma unroll
                for (int nt = 0; nt < 4; nt++) {
                    mma16816(acc[mt][nt], ah[mt], &bh[nt >> 1][(nt & 1) * 2]);
                    mma16816(acc[mt][nt], ah[mt], &bl[nt >> 1][(nt & 1) * 2]);
                }
            uint32_t al[4][4];
#pragma unroll
            for (int mt = 0; mt < 4; mt++)
                ldsm4(al[mt], pAlo + (aRow + mt * 16) * 80 + ko + aKof);
#pragma unroll
            for (int mt = 0; mt < 4; mt++)
#pragma unroll
                for (int nt = 0; nt < 4; nt++)
                    mma16816(acc[mt][nt], al[mt], &bh[nt >> 1][(nt & 1) * 2]);
        }
        __syncthreads();   // guard: next issue overwrites the other stage
    }

    const int g   = lane >> 2;
    const int tig = lane & 3;
#pragma unroll
    for (int mt = 0; mt < 4; mt++) {
        const int r0 = rowBase + wm * 64 + mt * 16 + g;
#pragma unroll
        for (int nt = 0; nt < 4; nt++) {
            const int col = colBase + wn * 32 + nt * 8 + tig * 2;
            const float b0 = bias[col], b1 = bias[col + 1];
            float2 o0 = make_float2(acc[mt][nt][0] + b0, acc[mt][nt][1] + b1);
            float2 o1 = make_float2(acc[mt][nt][2] + b0, acc[mt][nt][3] + b1);
            *(float2*)(C + (size_t)r0 * ldc + col)       = o0;
            *(float2*)(C + (size_t)(r0 + 8) * ldc + col) = o1;
        }
    }
}

// ---------------------------------------------------------------------------
// RoPE + scatter to bf16 hi/lo (unchanged)
// ---------------------------------------------------------------------------
__global__ __launch_bounds__(256)
void rope_scatter(const float* __restrict__ cosb, const float* __restrict__ sinb)
{
    const int idx = blockIdx.x * blockDim.x + threadIdx.x;
    const int total = NH * S_TOT * (HD / 2);
    if (idx >= total) return;
    const int d    = idx % (HD / 2);
    const int rest = idx / (HD / 2);
    const int s = rest % S_TOT;
    const int h = rest / S_TOT;

    const float c0 = cosb[s * HD + d];
    const float c1 = cosb[s * HD + d + 40];
    const float s0 = sinb[s * HD + d];
    const float s1 = sinb[s * HD + d + 40];

    const size_t src  = (size_t)s * N_QKV + h * HD + d;
    const size_t dstb = ((size_t)h * S_TOT + s) * HD + d;
    const float scale = 0.11180339887498948f;

    float q0 = g_qkv[src],       q1 = g_qkv[src + 40];
    float k0 = g_qkv[src + DIM], k1 = g_qkv[src + DIM + 40];

    float qa = (q0 * c0 - q1 * s0) * scale;
    float qb = (q1 * c1 + q0 * s1) * scale;
    float ka = k0 * c0 - k1 * s0;
    float kb = k1 * c1 + k0 * s1;

    __nv_bfloat16 h_, l_;
    split2(qa, h_, l_); g_qhi[dstb] = h_;      g_qlo[dstb] = l_;
    split2(qb, h_, l_); g_qhi[dstb + 40] = h_; g_qlo[dstb + 40] = l_;
    split2(ka, h_, l_); g_khi[dstb] = h_;      g_klo[dstb] = l_;
    split2(kb, h_, l_); g_khi[dstb + 40] = h_; g_klo[dstb + 40] = l_;
}

// ---------------------------------------------------------------------------
// V: split + transpose (unchanged)
// ---------------------------------------------------------------------------
__global__ __launch_bounds__(256)
void v_split_t()
{
    __shared__ float tile[32][33];
    const int t = threadIdx.x;
    const int sBase  = blockIdx.x * 32;
    const int hdBase = blockIdx.y * 32;

    const int tx = t & 31, ty = t >> 5;
#pragma unroll
    for (int j = 0; j < 4; j++) {
        const int r = ty + j * 8;
        tile[r][tx] = g_qkv[(size_t)(sBase + r) * N_QKV + 2 * DIM + hdBase + tx];
    }
    __syncthreads();

    const int r2 = t >> 3;
    const int sp = (t & 7) * 4;
    __nv_bfloat16 h0, h1, h2, h3, l0, l1, l2, l3;
    split2(tile[sp + 0][r2], h0, l0);
    split2(tile[sp + 1][r2], h1, l1);
    split2(tile[sp + 2][r2], h2, l2);
    split2(tile[sp + 3][r2], h3, l3);
    const size_t o = (size_t)(hdBase + r2) * S_TOT + sBase + sp;
    *(__nv_bfloat162*)(g_vhi + o)     = __nv_bfloat162(h0, h1);
    *(__nv_bfloat162*)(g_vhi + o + 2) = __nv_bfloat162(h2, h3);
    *(__nv_bfloat162*)(g_vlo + o)     = __nv_bfloat162(l0, l1);
    *(__nv_bfloat162*)(g_vlo + o + 2) = __nv_bfloat162(l2, l3);
}

// ---------------------------------------------------------------------------
// Tensor-core flash attention: register-resident P, cp.async double-buffered K/V.
// CTA: 128 q-rows x 1024 kv (8 chunks of 128). 8 warps, 16 rows each.
// SMEM: Q(hi+lo) + 2 x K-stage + 2 x V-stage = 222208 B.
// ---------------------------------------------------------------------------
#define AQH   0
#define AQL   22528                 // 128*88*2
#define AK0   45056                 // K stages (each 45056: KH + KL at +22528)
#define AKSZ  45056
#define AV0   135168                // V stages (each 43520: VH + VL at +21760)
#define AVSZ  43520
#define ATTN_SMEM 222208

__global__ __launch_bounds__(256)
void attn_mma()
{
    extern __shared__ char sm[];
    const uint32_t sb = smem_u32(sm);
    const int t    = threadIdx.x;
    const int wid  = t >> 5;
    const int lane = t & 31;
    const int qb = blockIdx.x, h = blockIdx.y, seg = blockIdx.z;
    const int segBase = seg * SEGL;
    const int s0 = segBase + qb * 128;

    // ---- load Q (persistent): 128 x 80 hi+lo, pitch 88 ----
    {
        const size_t qBase = ((size_t)h * S_TOT + s0) * HD;
#pragma unroll
        for (int j = 0; j < 5; j++) {
            const int idx = t + j * 256;        // 0..1279
            const int r  = idx / 10;
            const int c8 = (idx % 10) * 8;
            const size_t ga = qBase + (size_t)r * HD + c8;
            const uint32_t so = r * 176 + c8 * 2;
            *(uint4*)(sm + AQH + so) = *(const uint4*)(g_qhi + ga);
            *(uint4*)(sm + AQL + so) = *(const uint4*)(g_qlo + ga);
        }
    }

    auto issueKV = [&](int stage, int kc) {
        const uint32_t kb = sb + AK0 + stage * AKSZ;
        const uint32_t vb = sb + AV0 + stage * AVSZ;
#pragma unroll
        for (int j = 0; j < 5; j++) {
            const int idx = t + j * 256;
            const int r  = idx / 10;
            const int c8 = (idx % 10) * 8;
            const size_t ga = ((size_t)h * S_TOT + segBase + kc + r) * HD + c8;
            const uint32_t so = r * 176 + c8 * 2;
            cpa16(kb + so,         g_khi + ga);
            cpa16(kb + 22528 + so, g_klo + ga);
        }
#pragma unroll
        for (int j = 0; j < 5; j++) {
            const int idx = t + j * 256;
            const int r  = idx >> 4;            // 0..79
            const int c8 = (idx & 15) * 8;      // 0..120
            const size_t ga = ((size_t)(h * HD + r)) * S_TOT + segBase + kc + c8;
            const uint32_t so = r * 272 + c8 * 2;
            cpa16(vb + so,         g_vhi + ga);
            cpa16(vb + 21760 + so, g_vlo + ga);
        }
        cpa_commit();
    };

    const uint32_t aRowOff = (wid * 16 + (lane & 15));
    const uint32_t aKof = (lane >> 4) * 16;
    const uint32_t bRowSub = ((lane >> 4) ? 8 : 0) + (lane & 7);
    const uint32_t bKof = ((lane >> 3) & 1) * 16;

    const int g   = lane >> 2;
    const int tig = lane & 3;

    float m0 = -1e30f, m1 = -1e30f, l0 = 0.f, l1 = 0.f;
    float oacc[10][4] = {};

    issueKV(0, 0);
    for (int it = 0; it < 8; it++) {
        if (it < 7) { issueKV((it + 1) & 1, (it + 1) * 128); cpa_wait<1>(); }
        else        { cpa_wait<0>(); }
        __syncthreads();

        const uint32_t kH = sb + AK0 + (it & 1) * AKSZ;
        const uint32_t kL = kH + 22528;
        const uint32_t vH = sb + AV0 + (it & 1) * AVSZ;
        const uint32_t vL = vH + 21760;

        // ---- S = Q K^T (warp: 16 rows x 128 kv) ----
        float acc[16][4];
#pragma unroll
        for (int nt = 0; nt < 16; nt++)
#pragma unroll
            for (int c = 0; c < 4; c++) acc[nt][c] = 0.f;

#pragma unroll
        for (int ks = 0; ks < 5; ks++) {
            const uint32_t ko = ks * 32;
            uint32_t qh[4], ql[4];
            ldsm4(qh, sb + AQH + aRowOff * 176 + ko + aKof);
            ldsm4(ql, sb + AQL + aRowOff * 176 + ko + aKof);
#pragma unroll
            for (int bt = 0; bt < 8; bt++) {
                uint32_t kh[4], kl[4];
                const uint32_t br = (bt * 16 + bRowSub) * 176 + ko + bKof;
                ldsm4(kh, kH + br);
                ldsm4(kl, kL + br);
                mma16816(acc[2 * bt],     qh, kh + 0);
                mma16816(acc[2 * bt + 1], qh, kh + 2);
                mma16816(acc[2 * bt],     qh, kl + 0);
                mma16816(acc[2 * bt + 1], qh, kl + 2);
                mma16816(acc[2 * bt],     ql, kh + 0);
                mma16816(acc[2 * bt + 1], ql, kh + 2);
            }
        }

        // ---- online softmax ----
        float mx0 = -1e30f, mx1 = -1e30f;
#pragma unroll
        for (int nt = 0; nt < 16; nt++) {
            mx0 = fmaxf(mx0, fmaxf(acc[nt][0], acc[nt][1]));
            mx1 = fmaxf(mx1, fmaxf(acc[nt][2], acc[nt][3]));
        }
        mx0 = fmaxf(mx0, __shfl_xor_sync(0xffffffffu, mx0, 1));
        mx0 = fmaxf(mx0, __shfl_xor_sync(0xffffffffu, mx0, 2));
        mx1 = fmaxf(mx1, __shfl_xor_sync(0xffffffffu, mx1, 1));
        mx1 = fmaxf(mx1, __shfl_xor_sync(0xffffffffu, mx1, 2));

        const float mn0 = fmaxf(m0, mx0);
        const float mn1 = fmaxf(m1, mx1);
        const float cr0 = __expf(m0 - mn0);
        const float cr1 = __expf(m1 - mn1);
        m0 = mn0; m1 = mn1;

        float rs0 = 0.f, rs1 = 0.f;
#pragma unroll
        for (int nt = 0; nt < 16; nt++) {
            acc[nt][0] = __expf(acc[nt][0] - mn0);
            acc[nt][1] = __expf(acc[nt][1] - mn0);
            acc[nt][2] = __expf(acc[nt][2] - mn1);
            acc[nt][3] = __expf(acc[nt][3] - mn1);
            rs0 += acc[nt][0] + acc[nt][1];
            rs1 += acc[nt][2] + acc[nt][3];
        }
        rs0 += __shfl_xor_sync(0xffffffffu, rs0, 1);
        rs0 += __shfl_xor_sync(0xffffffffu, rs0, 2);
        rs1 += __shfl_xor_sync(0xffffffffu, rs1, 1);
        rs1 += __shfl_xor_sync(0xffffffffu, rs1, 2);
        l0 = l0 * cr0 + rs0;
        l1 = l1 * cr1 + rs1;

#pragma unroll
        for (int vt = 0; vt < 10; vt++) {
            oacc[vt][0] *= cr0; oacc[vt][1] *= cr0;
            oacc[vt][2] *= cr1; oacc[vt][3] *= cr1;
        }

        // ---- O += P V, P stays in registers (C-fragment == A-fragment layout) ----
#pragma unroll
        for (int ks = 0; ks < 8; ks++) {
            uint32_t ph[4], pl[4];
            packsplit(acc[2 * ks][0],     acc[2 * ks][1],     ph[0], pl[0]);
            packsplit(acc[2 * ks][2],     acc[2 * ks][3],     ph[1], pl[1]);
            packsplit(acc[2 * ks + 1][0], acc[2 * ks + 1][1], ph[2], pl[2]);
            packsplit(acc[2 * ks + 1][2], acc[2 * ks + 1][3], ph[3], pl[3]);
            const uint32_t ko = ks * 32;
#pragma unroll
            for (int bt = 0; bt < 5; bt++) {
                uint32_t vh[4], vl[4];
                const uint32_t br = (bt * 16 + bRowSub) * 272 + ko + bKof;
                ldsm4(vh, vH + br);
                ldsm4(vl, vL + br);
                mma16816(oacc[2 * bt],     ph, vh + 0);
                mma16816(oacc[2 * bt + 1], ph, vh + 2);
                mma16816(oacc[2 * bt],     ph, vl + 0);
                mma16816(oacc[2 * bt + 1], ph, vl + 2);
                mma16816(oacc[2 * bt],     pl, vh + 0);
                mma16816(oacc[2 * bt + 1], pl, vh + 2);
            }
        }
        __syncthreads();   // guard: next issue overwrites the other stage
    }

    // ---- epilogue: normalize, split, write proj-GEMM A operand ----
    const float inv0 = 1.0f / l0;
    const float inv1 = 1.0f / l1;
    const int srow0 = s0 + wid * 16 + g;
    const int srow1 = srow0 + 8;
#pragma unroll
    for (int vt = 0; vt < 10; vt++) {
        const int col = h * HD + vt * 8 + tig * 2;
        __nv_bfloat16 h0, lo0, h1, lo1;
        split2(oacc[vt][0] * inv0, h0, lo0);
        split2(oacc[vt][1] * inv0, h1, lo1);
        *(__nv_bfloat162*)(g_ahi + (size_t)srow0 * DIM + col) = __nv_bfloat162(h0, h1);
        *(__nv_bfloat162*)(g_alo + (size_t)srow0 * DIM + col) = __nv_bfloat162(lo0, lo1);
        split2(oacc[vt][2] * inv1, h0, lo0);
        split2(oacc[vt][3] * inv1, h1, lo1);
        *(__nv_bfloat162*)(g_ahi + (size_t)srow1 * DIM + col) = __nv_bfloat162(h0, h1);
        *(__nv_bfloat162*)(g_alo + (size_t)srow1 * DIM + col) = __nv_bfloat162(lo0, lo1);
    }
}

// ---------------------------------------------------------------------------
extern "C" void kernel_launch(void* const* d_in, const int* in_sizes, int n_in,
                              void* d_out, int out_size)
{
    const float* hidden = (const float*)d_in[0];
    const float* cosb   = (const float*)d_in[2];
    const float* sinb   = (const float*)d_in[3];
    const float* qkv_w  = (const float*)d_in[4];
    const float* qkv_b  = (const float*)d_in[5];
    const float* proj_w = (const float*)d_in[6];
    const float* proj_b = (const float*)d_in[7];
    float* out = (float*)d_out;

    float* p_qkv;
    __nv_bfloat16 *p_ahi, *p_alo, *p_wqhi, *p_wqlo, *p_wphi, *p_wplo;
    cudaGetSymbolAddress((void**)&p_qkv,  g_qkv);
    cudaGetSymbolAddress((void**)&p_ahi,  g_ahi);
    cudaGetSymbolAddress((void**)&p_alo,  g_alo);
    cudaGetSymbolAddress((void**)&p_wqhi, g_wqhi);
    cudaGetSymbolAddress((void**)&p_wqlo, g_wqlo);
    cudaGetSymbolAddress((void**)&p_wphi, g_wphi);
    cudaGetSymbolAddress((void**)&p_wplo, g_wplo);

    cudaFuncSetAttribute(attn_mma,
                         cudaFuncAttributeMaxDynamicSharedMemorySize, ATTN_SMEM);
    cudaFuncSetAttribute(gemm_mma,
                         cudaFuncAttributeMaxDynamicSharedMemorySize, GEMM_SMEM);

    // 1) split inputs to bf16 hi/lo
    {
        int n4 = S_TOT * DIM / 4;
        split_kernel<<<(n4 + 255) / 256, 256>>>(hidden, p_ahi, p_alo, n4);
        n4 = N_QKV * DIM / 4;
        split_kernel<<<(n4 + 255) / 256, 256>>>(qkv_w, p_wqhi, p_wqlo, n4);
        n4 = DIM * DIM / 4;
        split_kernel<<<(n4 + 255) / 256, 256>>>(proj_w, p_wphi, p_wplo, n4);
    }

    // 2) QKV GEMM (cp.async 2-stage)
    gemm_mma<<<dim3(N_QKV / 128, S_TOT / 128), 256, GEMM_SMEM>>>(
        p_ahi, p_alo, p_wqhi, p_wqlo, qkv_b, p_qkv, N_QKV);

    // 3) RoPE+split (q,k) and V transpose+split
    {
        const int total = NH * S_TOT * (HD / 2);
        rope_scatter<<<(total + 255) / 256, 256>>>(cosb, sinb);
        v_split_t<<<dim3(S_TOT / 32, DIM / 32), 256>>>();
    }

    // 4) attention (register-P, double-buffered K/V) -> writes g_ahi/g_alo
    attn_mma<<<dim3(SEGL / 128, NH, NSEG), 256, ATTN_SMEM>>>();

    // 5) output projection
    gemm_mma<<<dim3(DIM / 128, S_TOT / 128), 256, GEMM_SMEM>>>(
        p_ahi, p_alo, p_wphi, p_wplo, proj_b, out, DIM);
}